// round 1
// baseline (speedup 1.0000x reference)
#include <cuda_runtime.h>
#include <cuda_bf16.h>
#include <cstdint>

// ---------------- problem constants ----------------
#define BATCH 4
#define SEQ   4096
#define CDIM  512
#define NHEAD 8
#define HDIM  64
#define WIN   15
#define PADW  7
#define TPAD  (SEQ + 2*PADW)          // 4110
#define MQ    (BATCH*SEQ)             // 16384
#define MKV   (BATCH*TPAD)            // 16440
#define KDIM  CDIM                    // 512
#define ATT_SCALE 0.04231328439222203f  // ln(15)/64

// ---------------- scratch (device globals: no allocs allowed) ----------------
__device__ float g_q  [(size_t)MQ  * CDIM];          // 32 MB
__device__ float g_kv [(size_t)MKV * 2 * CDIM];      // 67 MB  [k(512) | v(512)] per padded row
__device__ float g_att[(size_t)MQ  * CDIM];          // 32 MB

// ---------------- GEMM tiling ----------------
#define BM 128
#define BN 64
#define BK 32
#define BK2 (BK/2)      // 16 packed bf16x2 columns per tile
#define ASTRIDE 20      // uint32 stride for As rows (conflict-free frag loads)
#define BSTRIDE 72      // uint32 stride for Bs rows (conflict-free frag loads)

__device__ __forceinline__ uint32_t pack2_bf16(float even_k, float odd_k) {
    // d[15:0] = convert(second operand) -> even k in low half (matches mma frag order)
    uint32_t r;
    asm("cvt.rn.bf16x2.f32 %0, %1, %2;" : "=r"(r) : "f"(odd_k), "f"(even_k));
    return r;
}

__device__ __forceinline__ void split_bf16(float x, float& hi, float& lo) {
    __nv_bfloat16 h = __float2bfloat16_rn(x);
    hi = __bfloat162float(h);
    lo = x - hi;
}

__device__ __forceinline__ void mma_bf16(float* c, const uint32_t* a, const uint32_t* b) {
    asm volatile(
        "mma.sync.aligned.m16n8k16.row.col.f32.bf16.bf16.f32 "
        "{%0,%1,%2,%3}, {%4,%5,%6,%7}, {%8,%9}, {%0,%1,%2,%3};\n"
        : "+f"(c[0]), "+f"(c[1]), "+f"(c[2]), "+f"(c[3])
        : "r"(a[0]), "r"(a[1]), "r"(a[2]), "r"(a[3]), "r"(b[0]), "r"(b[1]));
}

// MODE 0: q = (x*mask) @ Wq + bq            -> g_q     (M=MQ,  N=512)
// MODE 1: kv = pad(x*mask) @ Wkv + bkv      -> g_kv    (M=MKV, N=1024), zero rows at pad
// MODE 2: out = (g_att @ Wproj + bproj)*mask -> Cout   (M=MQ,  N=512)
template<int MODE>
__global__ __launch_bounds__(256, 2)
void gemm_kernel(const float* __restrict__ A, const float* __restrict__ W,
                 const float* __restrict__ bias, const float* __restrict__ mask,
                 float* __restrict__ Cout, int Mrows, int N)
{
    __shared__ __align__(16) uint32_t As_hi[BM][ASTRIDE];
    __shared__ __align__(16) uint32_t As_lo[BM][ASTRIDE];
    __shared__ __align__(16) uint32_t Bs_hi[BK2][BSTRIDE];
    __shared__ __align__(16) uint32_t Bs_lo[BK2][BSTRIDE];

    const int tid  = threadIdx.x;
    const int warp = tid >> 5;
    const int lane = tid & 31;
    const int wm   = warp & 1;       // 0..1 : 64-row slab
    const int wn   = warp >> 1;      // 0..3 : 16-col slab
    const int g    = lane >> 2;      // groupID 0..7
    const int tq   = lane & 3;       // 0..3

    const int blockN = blockIdx.x * BN;
    const int blockM = blockIdx.y * BM;

    const float* Abase = (MODE == 2) ? g_att : A;
    float* Op = (MODE == 0) ? g_q : (MODE == 1) ? g_kv : Cout;

    // ---- per-thread A-load row mapping (4 rows, constant over k) ----
    const int arow = tid >> 3;       // 0..31
    const int akg  = tid & 7;        // 0..7 : 4-float group within 32 k
    const float* arowp[4];
    float asc[4];
    #pragma unroll
    for (int r4 = 0; r4 < 4; ++r4) {
        int grow = blockM + arow + 32*r4;
        const float* ap = nullptr; float sc = 0.f;
        if (grow < Mrows) {
            if (MODE == 1) {
                int bb = grow / TPAD;
                int p  = grow - bb*TPAD;
                int t  = p - PADW;
                if (t >= 0 && t < SEQ) {
                    int src = bb*SEQ + t;
                    ap = Abase + (size_t)src*KDIM;
                    sc = mask[src];
                }
            } else {
                ap = Abase + (size_t)grow*KDIM;
                sc = (MODE == 0) ? mask[grow] : 1.0f;
            }
        }
        arowp[r4] = ap; asc[r4] = sc;
    }

    const int bkp = tid >> 4;        // 0..15 : packed k row
    const int bcg = tid & 15;        // 0..15 : 4-col group

    float acc[4][2][4];
    #pragma unroll
    for (int mi = 0; mi < 4; ++mi)
        #pragma unroll
        for (int ni = 0; ni < 2; ++ni)
            #pragma unroll
            for (int r = 0; r < 4; ++r) acc[mi][ni][r] = 0.f;

    for (int k0 = 0; k0 < KDIM; k0 += BK) {
        // ---- stage A tile: split into bf16 hi/lo pairs ----
        #pragma unroll
        for (int r4 = 0; r4 < 4; ++r4) {
            float4 v = make_float4(0.f, 0.f, 0.f, 0.f);
            if (arowp[r4]) {
                v = *reinterpret_cast<const float4*>(arowp[r4] + k0 + akg*4);
                v.x *= asc[r4]; v.y *= asc[r4]; v.z *= asc[r4]; v.w *= asc[r4];
            }
            float hx, lx, hy, ly, hz, lz, hw, lw;
            split_bf16(v.x, hx, lx); split_bf16(v.y, hy, ly);
            split_bf16(v.z, hz, lz); split_bf16(v.w, hw, lw);
            int row = arow + 32*r4;
            *reinterpret_cast<uint2*>(&As_hi[row][akg*2]) =
                make_uint2(pack2_bf16(hx, hy), pack2_bf16(hz, hw));
            *reinterpret_cast<uint2*>(&As_lo[row][akg*2]) =
                make_uint2(pack2_bf16(lx, ly), pack2_bf16(lz, lw));
        }
        // ---- stage B tile ----
        {
            const float* wr0 = W + (size_t)(k0 + 2*bkp) * N + blockN + bcg*4;
            float4 r0 = *reinterpret_cast<const float4*>(wr0);
            float4 r1 = *reinterpret_cast<const float4*>(wr0 + N);
            float h0,l0,h1,l1,h2,l2,h3,l3, g0,m0,g1,m1,g2,m2,g3,m3;
            split_bf16(r0.x, h0, l0); split_bf16(r0.y, h1, l1);
            split_bf16(r0.z, h2, l2); split_bf16(r0.w, h3, l3);
            split_bf16(r1.x, g0, m0); split_bf16(r1.y, g1, m1);
            split_bf16(r1.z, g2, m2); split_bf16(r1.w, g3, m3);
            *reinterpret_cast<uint4*>(&Bs_hi[bkp][bcg*4]) = make_uint4(
                pack2_bf16(h0, g0), pack2_bf16(h1, g1),
                pack2_bf16(h2, g2), pack2_bf16(h3, g3));
            *reinterpret_cast<uint4*>(&Bs_lo[bkp][bcg*4]) = make_uint4(
                pack2_bf16(l0, m0), pack2_bf16(l1, m1),
                pack2_bf16(l2, m2), pack2_bf16(l3, m3));
        }
        __syncthreads();

        // ---- compute: 2 k16 steps per tile ----
        #pragma unroll
        for (int kk2 = 0; kk2 < BK2; kk2 += 8) {
            uint32_t ah[4][4], al[4][4];
            #pragma unroll
            for (int mi = 0; mi < 4; ++mi) {
                int m0r = wm*64 + mi*16 + g;
                ah[mi][0] = As_hi[m0r    ][kk2 + tq];
                ah[mi][1] = As_hi[m0r + 8][kk2 + tq];
                ah[mi][2] = As_hi[m0r    ][kk2 + tq + 4];
                ah[mi][3] = As_hi[m0r + 8][kk2 + tq + 4];
                al[mi][0] = As_lo[m0r    ][kk2 + tq];
                al[mi][1] = As_lo[m0r + 8][kk2 + tq];
                al[mi][2] = As_lo[m0r    ][kk2 + tq + 4];
                al[mi][3] = As_lo[m0r + 8][kk2 + tq + 4];
            }
            uint32_t bh[2][2], bl[2][2];
            #pragma unroll
            for (int ni = 0; ni < 2; ++ni) {
                int c0 = wn*16 + ni*8 + g;
                bh[ni][0] = Bs_hi[kk2 + tq    ][c0];
                bh[ni][1] = Bs_hi[kk2 + tq + 4][c0];
                bl[ni][0] = Bs_lo[kk2 + tq    ][c0];
                bl[ni][1] = Bs_lo[kk2 + tq + 4][c0];
            }
            #pragma unroll
            for (int mi = 0; mi < 4; ++mi)
                #pragma unroll
                for (int ni = 0; ni < 2; ++ni) {
                    mma_bf16(acc[mi][ni], ah[mi], bh[ni]);   // hi*hi
                    mma_bf16(acc[mi][ni], ah[mi], bl[ni]);   // hi*lo
                    mma_bf16(acc[mi][ni], al[mi], bh[ni]);   // lo*hi
                }
        }
        __syncthreads();
    }

    // ---- epilogue: bias (+ optional output mask) ----
    #pragma unroll
    for (int mi = 0; mi < 4; ++mi) {
        int row0 = blockM + wm*64 + mi*16 + g;
        int row1 = row0 + 8;
        #pragma unroll
        for (int ni = 0; ni < 2; ++ni) {
            int col = blockN + wn*16 + ni*8 + 2*tq;
            float bv0 = bias[col], bv1 = bias[col + 1];
            if (row0 < Mrows) {
                float s0 = (MODE == 2) ? mask[row0] : 1.0f;
                Op[(size_t)row0*N + col    ] = (acc[mi][ni][0] + bv0) * s0;
                Op[(size_t)row0*N + col + 1] = (acc[mi][ni][1] + bv1) * s0;
            }
            if (row1 < Mrows) {
                float s1 = (MODE == 2) ? mask[row1] : 1.0f;
                Op[(size_t)row1*N + col    ] = (acc[mi][ni][2] + bv0) * s1;
                Op[(size_t)row1*N + col + 1] = (acc[mi][ni][3] + bv1) * s1;
            }
        }
    }
}

// ---------------- windowed attention: 1 warp per (b,t,h) ----------------
__global__ __launch_bounds__(256)
void attn_kernel()
{
    const int bt   = blockIdx.x;           // 0..MQ-1
    const int b    = bt >> 12;             // / SEQ
    const int t    = bt & (SEQ - 1);
    const int h    = threadIdx.x >> 5;
    const int lane = threadIdx.x & 31;

    const float* qp = g_q + (size_t)bt*CDIM + h*HDIM + 2*lane;
    const float q0 = qp[0], q1 = qp[1];

    const size_t kvbase = ((size_t)(b*TPAD + t)) * (2*CDIM) + h*HDIM + 2*lane;

    float s[WIN];
    #pragma unroll
    for (int w = 0; w < WIN; ++w) {
        const float* kp = g_kv + kvbase + (size_t)w * (2*CDIM);
        float p = q0*kp[0] + q1*kp[1];
        p += __shfl_xor_sync(0xffffffffu, p, 16);
        p += __shfl_xor_sync(0xffffffffu, p, 8);
        p += __shfl_xor_sync(0xffffffffu, p, 4);
        p += __shfl_xor_sync(0xffffffffu, p, 2);
        p += __shfl_xor_sync(0xffffffffu, p, 1);
        s[w] = p * ATT_SCALE;
    }
    float mx = s[0];
    #pragma unroll
    for (int w = 1; w < WIN; ++w) mx = fmaxf(mx, s[w]);
    float sum = 0.f;
    #pragma unroll
    for (int w = 0; w < WIN; ++w) { s[w] = expf(s[w] - mx); sum += s[w]; }
    const float inv = 1.f / sum;

    float o0 = 0.f, o1 = 0.f;
    #pragma unroll
    for (int w = 0; w < WIN; ++w) {
        const float* vp = g_kv + kvbase + CDIM + (size_t)w * (2*CDIM);
        float a = s[w] * inv;
        o0 += a * vp[0];
        o1 += a * vp[1];
    }
    float* op = g_att + (size_t)bt*CDIM + h*HDIM + 2*lane;
    op[0] = o0; op[1] = o1;
}

// ---------------- launch ----------------
extern "C" void kernel_launch(void* const* d_in, const int* in_sizes, int n_in,
                              void* d_out, int out_size)
{
    const float* x     = (const float*)d_in[0];
    const float* mask  = (const float*)d_in[1];
    const float* Wq    = (const float*)d_in[2];
    const float* bq    = (const float*)d_in[3];
    const float* Wkv   = (const float*)d_in[4];
    const float* bkv   = (const float*)d_in[5];
    const float* Wproj = (const float*)d_in[6];
    const float* bproj = (const float*)d_in[7];
    float* out = (float*)d_out;

    dim3 blk(256);

    // q = (x*mask) @ Wq + bq
    gemm_kernel<0><<<dim3(CDIM/BN, MQ/BM), blk>>>(x, Wq, bq, mask, nullptr, MQ, CDIM);
    // kv = pad(x*mask) @ Wkv + bkv  (padded rows -> bias only)
    gemm_kernel<1><<<dim3(2*CDIM/BN, (MKV + BM - 1)/BM), blk>>>(x, Wkv, bkv, mask, nullptr, MKV, 2*CDIM);
    // windowed softmax attention
    attn_kernel<<<MQ, 256>>>();
    // out = (att @ Wproj + bproj) * mask
    gemm_kernel<2><<<dim3(CDIM/BN, MQ/BM), blk>>>(nullptr, Wproj, bproj, mask, out, MQ, CDIM);
}

// round 3
// speedup vs baseline: 1.3994x; 1.3994x over previous
#include <cuda_runtime.h>
#include <cuda_bf16.h>
#include <cstdint>

// ---------------- problem constants ----------------
#define BATCH 4
#define SEQ   4096
#define CDIM  512
#define NHEAD 8
#define HDIM  64
#define WIN   15
#define PADW  7
#define TPAD  (SEQ + 2*PADW)          // 4110
#define MQ    (BATCH*SEQ)             // 16384
#define MKV   (BATCH*TPAD)            // 16440
#define ATT_SCALE 0.04231328439222203f  // ln(15)/64

// ---------------- scratch (device globals: no allocs allowed) ----------------
__device__ float g_q  [(size_t)MQ  * CDIM];            // fp32 q
__device__ float g_kv [(size_t)MKV * 2 * CDIM];        // fp32 [k(512) | v(512)] per padded row
__device__ __nv_bfloat16 g_x_hi [(size_t)MQ * CDIM];   // split of x*mask
__device__ __nv_bfloat16 g_x_lo [(size_t)MQ * CDIM];
__device__ __nv_bfloat16 g_att_hi[(size_t)MQ * CDIM];  // split of attention output
__device__ __nv_bfloat16 g_att_lo[(size_t)MQ * CDIM];
// transposed weights, bf16 hi/lo: [N][K=512]; offsets: q:0, kv:262144, proj:786432
__device__ __nv_bfloat16 g_wT_hi[1048576];
__device__ __nv_bfloat16 g_wT_lo[1048576];
#define WQ_OFF    0
#define WKV_OFF   262144
#define WPROJ_OFF 786432

// ---------------- helpers ----------------
__device__ __forceinline__ uint32_t smem_u32(const void* p) {
    uint32_t a;
    asm("{ .reg .u64 t; cvta.to.shared.u64 t, %1; cvt.u32.u64 %0, t; }" : "=r"(a) : "l"(p));
    return a;
}
__device__ __forceinline__ uint32_t pack2_bf16(float even_k, float odd_k) {
    uint32_t r;
    asm("cvt.rn.bf16x2.f32 %0, %1, %2;" : "=r"(r) : "f"(odd_k), "f"(even_k));
    return r;
}
__device__ __forceinline__ void split_bf16(float x, float& hi, float& lo) {
    __nv_bfloat16 h = __float2bfloat16_rn(x);
    hi = __bfloat162float(h);
    lo = x - hi;
}
__device__ __forceinline__ uint32_t swz128(uint32_t off) { return off ^ ((off >> 3) & 0x70); }

__device__ __forceinline__ void cpa16(uint32_t dst, const void* src, uint32_t src_sz) {
    asm volatile("cp.async.cg.shared.global [%0], [%1], 16, %2;"
                 :: "r"(dst), "l"(src), "r"(src_sz) : "memory");
}
__device__ __forceinline__ void cp_commit() {
    asm volatile("cp.async.commit_group;" ::: "memory");
}
template<int N>
__device__ __forceinline__ void cp_wait() {
    asm volatile("cp.async.wait_group %0;" :: "n"(N) : "memory");
}
__device__ __forceinline__ void ldsm_x4(uint32_t* r, uint32_t addr) {
    asm volatile("ldmatrix.sync.aligned.m8n8.x4.shared.b16 {%0,%1,%2,%3}, [%4];"
                 : "=r"(r[0]), "=r"(r[1]), "=r"(r[2]), "=r"(r[3]) : "r"(addr));
}
__device__ __forceinline__ void mma_bf16(float* c, const uint32_t* a, const uint32_t* b) {
    asm volatile(
        "mma.sync.aligned.m16n8k16.row.col.f32.bf16.bf16.f32 "
        "{%0,%1,%2,%3}, {%4,%5,%6,%7}, {%8,%9}, {%0,%1,%2,%3};\n"
        : "+f"(c[0]), "+f"(c[1]), "+f"(c[2]), "+f"(c[3])
        : "r"(a[0]), "r"(a[1]), "r"(a[2]), "r"(a[3]), "r"(b[0]), "r"(b[1]));
}

// ---------------- split kernels ----------------
__global__ void xsplit_kernel(const float* __restrict__ x, const float* __restrict__ mask) {
    size_t i = ((size_t)blockIdx.x * 256 + threadIdx.x) * 4;
    int row = (int)(i >> 9);
    float m = mask[row];
    float4 v = *reinterpret_cast<const float4*>(x + i);
    v.x *= m; v.y *= m; v.z *= m; v.w *= m;
    float hx,lx,hy,ly,hz,lz,hw,lw;
    split_bf16(v.x, hx, lx); split_bf16(v.y, hy, ly);
    split_bf16(v.z, hz, lz); split_bf16(v.w, hw, lw);
    *reinterpret_cast<uint2*>(g_x_hi + i) = make_uint2(pack2_bf16(hx, hy), pack2_bf16(hz, hw));
    *reinterpret_cast<uint2*>(g_x_lo + i) = make_uint2(pack2_bf16(lx, ly), pack2_bf16(lz, lw));
}

// W [K=512, N] row-major -> WT_hi/lo [N, 512] bf16 at g_wT_*[out_off]
__global__ void wsplit_kernel(const float* __restrict__ W, int out_off, int N) {
    __shared__ float tile[32][33];
    const int tx = threadIdx.x, ty = threadIdx.y;
    const int n0 = blockIdx.x * 32, k0 = blockIdx.y * 32;
    #pragma unroll
    for (int j = 0; j < 32; j += 8)
        tile[ty + j][tx] = W[(size_t)(k0 + ty + j) * N + n0 + tx];
    __syncthreads();
    #pragma unroll
    for (int j = 0; j < 32; j += 8) {
        float v = tile[tx][ty + j];
        float h, l; split_bf16(v, h, l);
        size_t o = (size_t)out_off + (size_t)(n0 + ty + j) * CDIM + k0 + tx;
        g_wT_hi[o] = __float2bfloat16_rn(h);
        g_wT_lo[o] = __float2bfloat16_rn(l);
    }
}

// ---------------- mma.sync GEMM: C[M,N] = A[M,512] @ WT[N,512]^T ----------------
// CTA 128x64, 8 warps (4m x 2n), warp tile 32x32. BK=64, 2-stage cp.async.
// stage layout (49152 B each): As_hi 16K | As_lo 16K | Bs_hi 8K | Bs_lo 8K
#define STAGE_BYTES 49152
#define GSMEM (2*STAGE_BYTES)

// MODE 0: g_q  (A=x_split),   MODE 1: g_kv (A=pad(x_split)),  MODE 2: OutP (A=att_split, *mask)
template<int MODE, bool THREE>
__global__ __launch_bounds__(256, 2)
void gemm_tc(const float* __restrict__ bias, const float* __restrict__ mask,
             float* __restrict__ OutP, int woff, int ncol0, int ldo, int Mrows)
{
    extern __shared__ __align__(1024) char smem[];
    const uint32_t sb = smem_u32(smem);
    const int tid = threadIdx.x, wid = tid >> 5, lane = tid & 31;
    const int wm = wid & 3, wn = wid >> 2;
    const int g = lane >> 2, tq = lane & 3;

    const int blockN = blockIdx.x * 64;     // local col within this output slice
    const int blockM = blockIdx.y * 128;

    const __nv_bfloat16* Ah = (MODE == 2) ? g_att_hi : g_x_hi;
    const __nv_bfloat16* Al = (MODE == 2) ? g_att_lo : g_x_lo;

    // ---- A staging map: thread t -> row rA = t>>1, segs (t&1)*4 .. +3 ----
    const int rA   = tid >> 1;
    const int asg0 = (tid & 1) * 4;
    const __nv_bfloat16 *aph, *apl;
    uint32_t szA = 0;
    {
        int grow = blockM + rA;
        int src = -1;
        if (grow < Mrows) {
            if (MODE == 1) {
                int bb = grow / TPAD;
                int p  = grow - bb * TPAD;
                int t  = p - PADW;
                if (t >= 0 && t < SEQ) src = bb * SEQ + t;
            } else src = grow;
        }
        if (src >= 0) {
            aph = Ah + (size_t)src * CDIM; apl = Al + (size_t)src * CDIM; szA = 16;
        } else { aph = Ah; apl = Al; }
    }
    // ---- B staging map: thread t -> n row nB = t>>2, segs (t&3)*2 .. +1 ----
    const int nB   = tid >> 2;
    const int bsg0 = (tid & 3) * 2;
    const __nv_bfloat16* bph = g_wT_hi + woff + (size_t)(blockN + nB) * CDIM;
    const __nv_bfloat16* bpl = g_wT_lo + woff + (size_t)(blockN + nB) * CDIM;

    float acc[2][4][4];
    #pragma unroll
    for (int mt = 0; mt < 2; ++mt)
        #pragma unroll
        for (int nt = 0; nt < 4; ++nt)
            #pragma unroll
            for (int r = 0; r < 4; ++r) acc[mt][nt][r] = 0.f;

    // issue one k-chunk of cp.asyncs
    auto issue = [&](int c) {
        const uint32_t st = sb + (uint32_t)(c & 1) * STAGE_BYTES;
        #pragma unroll
        for (int i = 0; i < 4; ++i) {
            int seg = asg0 + i;
            uint32_t dsw = swz128((uint32_t)(rA * 128 + seg * 16));
            cpa16(st + dsw, aph + c * 64 + seg * 8, szA);
            if (THREE) cpa16(st + 16384 + dsw, apl + c * 64 + seg * 8, szA);
        }
        #pragma unroll
        for (int i = 0; i < 2; ++i) {
            int seg = bsg0 + i;
            uint32_t dsw = swz128((uint32_t)(nB * 128 + seg * 16));
            cpa16(st + 32768 + dsw, bph + c * 64 + seg * 8, 16);
            if (THREE) cpa16(st + 40960 + dsw, bpl + c * 64 + seg * 8, 16);
        }
        cp_commit();
    };

    issue(0); issue(1);

    const int lr = (lane & 7) + ((lane >> 3) & 1) * 8;
    const int kl = (lane >> 4) * 16;

    #pragma unroll 1
    for (int c = 0; c < 8; ++c) {
        if (c == 7) cp_wait<0>(); else cp_wait<1>();
        __syncthreads();

        const uint32_t stA  = sb + (uint32_t)(c & 1) * STAGE_BYTES;
        const uint32_t stAl = stA + 16384;
        const uint32_t stB  = stA + 32768;
        const uint32_t stBl = stA + 40960;

        #pragma unroll
        for (int kk = 0; kk < 4; ++kk) {
            const int ko = kk * 32 + kl;
            uint32_t ahf[2][4], alf[2][4], bhf[2][4], blf[2][4];
            #pragma unroll
            for (int mt = 0; mt < 2; ++mt) {
                uint32_t off = swz128((uint32_t)((wm*32 + mt*16 + lr) * 128 + ko));
                ldsm_x4(ahf[mt], stA + off);
                if (THREE) ldsm_x4(alf[mt], stAl + off);
            }
            #pragma unroll
            for (int p = 0; p < 2; ++p) {
                uint32_t off = swz128((uint32_t)((wn*32 + p*16 + lr) * 128 + ko));
                ldsm_x4(bhf[p], stB + off);
                if (THREE) ldsm_x4(blf[p], stBl + off);
            }
            #pragma unroll
            for (int mt = 0; mt < 2; ++mt)
                #pragma unroll
                for (int nt = 0; nt < 4; ++nt) {
                    const int p = nt >> 1, j = nt & 1;
                    uint32_t bh2[2] = { bhf[p][j], bhf[p][j + 2] };
                    mma_bf16(acc[mt][nt], ahf[mt], bh2);
                    if (THREE) {
                        uint32_t bl2[2] = { blf[p][j], blf[p][j + 2] };
                        mma_bf16(acc[mt][nt], ahf[mt], bl2);   // hi*lo
                        mma_bf16(acc[mt][nt], alf[mt], bh2);   // lo*hi
                    }
                }
        }
        __syncthreads();
        if (c + 2 < 8) issue(c + 2);
    }

    // ---- epilogue ----
    float* Out = (MODE == 0) ? g_q : (MODE == 1) ? g_kv : OutP;
    #pragma unroll
    for (int mt = 0; mt < 2; ++mt) {
        const int r0 = blockM + wm*32 + mt*16 + g;
        const int r1 = r0 + 8;
        #pragma unroll
        for (int nt = 0; nt < 4; ++nt) {
            const int col = blockN + wn*32 + nt*8 + 2*tq;
            const float bv0 = bias[col], bv1 = bias[col + 1];
            if (r0 < Mrows) {
                float sc = (MODE == 2) ? mask[r0] : 1.0f;
                *reinterpret_cast<float2*>(Out + (size_t)r0*ldo + ncol0 + col) =
                    make_float2((acc[mt][nt][0] + bv0) * sc, (acc[mt][nt][1] + bv1) * sc);
            }
            if (r1 < Mrows) {
                float sc = (MODE == 2) ? mask[r1] : 1.0f;
                *reinterpret_cast<float2*>(Out + (size_t)r1*ldo + ncol0 + col) =
                    make_float2((acc[mt][nt][2] + bv0) * sc, (acc[mt][nt][3] + bv1) * sc);
            }
        }
    }
}

// ---------------- windowed attention: CTA = (b, h, 32 t's), K/V tiled in smem ----------------
__global__ __launch_bounds__(256)
void attn_kernel()
{
    __shared__ float sk[46 * 64];
    __shared__ float sv[46 * 64];

    const int t0 = blockIdx.x * 32;
    const int h  = blockIdx.y;
    const int b  = blockIdx.z;
    const int tid = threadIdx.x;

    // load 46 rows x 64 dims of k and v for this head
    {
        const size_t rowbase = (size_t)(b * TPAD + t0) * (2 * CDIM) + h * HDIM;
        for (int i = tid; i < 46 * 16; i += 256) {
            int r = i >> 4, s = i & 15;
            const float4* kp = reinterpret_cast<const float4*>(g_kv + rowbase + (size_t)r * (2*CDIM)) + s;
            const float4* vp = reinterpret_cast<const float4*>(g_kv + rowbase + (size_t)r * (2*CDIM) + CDIM) + s;
            reinterpret_cast<float4*>(sk)[i] = *kp;
            reinterpret_cast<float4*>(sv)[i] = *vp;
        }
    }
    __syncthreads();

    const int warp = tid >> 5, lane = tid & 31;

    #pragma unroll
    for (int j = 0; j < 4; ++j) {
        const int tl = warp * 4 + j;
        const int t  = t0 + tl;
        const size_t qoff = (size_t)(b * SEQ + t) * CDIM + h * HDIM + 2 * lane;
        const float2 qv = *reinterpret_cast<const float2*>(g_q + qoff);

        float s[WIN];
        #pragma unroll
        for (int w = 0; w < WIN; ++w) {
            const float2 kv2 = *reinterpret_cast<const float2*>(&sk[(tl + w) * 64 + 2 * lane]);
            float p = qv.x * kv2.x + qv.y * kv2.y;
            p += __shfl_xor_sync(0xffffffffu, p, 16);
            p += __shfl_xor_sync(0xffffffffu, p, 8);
            p += __shfl_xor_sync(0xffffffffu, p, 4);
            p += __shfl_xor_sync(0xffffffffu, p, 2);
            p += __shfl_xor_sync(0xffffffffu, p, 1);
            s[w] = p * ATT_SCALE;
        }
        float mx = s[0];
        #pragma unroll
        for (int w = 1; w < WIN; ++w) mx = fmaxf(mx, s[w]);
        float sum = 0.f;
        #pragma unroll
        for (int w = 0; w < WIN; ++w) { s[w] = __expf(s[w] - mx); sum += s[w]; }
        const float inv = 1.f / sum;

        float o0 = 0.f, o1 = 0.f;
        #pragma unroll
        for (int w = 0; w < WIN; ++w) {
            const float2 vv = *reinterpret_cast<const float2*>(&sv[(tl + w) * 64 + 2 * lane]);
            const float a = s[w] * inv;
            o0 += a * vv.x;
            o1 += a * vv.y;
        }
        float h0, l0, h1, l1;
        split_bf16(o0, h0, l0);
        split_bf16(o1, h1, l1);
        *reinterpret_cast<uint32_t*>(g_att_hi + qoff) = pack2_bf16(h0, h1);
        *reinterpret_cast<uint32_t*>(g_att_lo + qoff) = pack2_bf16(l0, l1);
    }
}

// ---------------- launch ----------------
extern "C" void kernel_launch(void* const* d_in, const int* in_sizes, int n_in,
                              void* d_out, int out_size)
{
    const float* x     = (const float*)d_in[0];
    const float* mask  = (const float*)d_in[1];
    const float* Wq    = (const float*)d_in[2];
    const float* bq    = (const float*)d_in[3];
    const float* Wkv   = (const float*)d_in[4];
    const float* bkv   = (const float*)d_in[5];
    const float* Wproj = (const float*)d_in[6];
    const float* bproj = (const float*)d_in[7];
    float* out = (float*)d_out;

    cudaFuncSetAttribute(gemm_tc<0,false>, cudaFuncAttributeMaxDynamicSharedMemorySize, GSMEM);
    cudaFuncSetAttribute(gemm_tc<1,false>, cudaFuncAttributeMaxDynamicSharedMemorySize, GSMEM);
    cudaFuncSetAttribute(gemm_tc<1,true>,  cudaFuncAttributeMaxDynamicSharedMemorySize, GSMEM);
    cudaFuncSetAttribute(gemm_tc<2,true>,  cudaFuncAttributeMaxDynamicSharedMemorySize, GSMEM);

    // weight transpose + split (tiny)
    wsplit_kernel<<<dim3(512/32, 512/32), dim3(32, 8)>>>(Wq,    WQ_OFF,    512);
    wsplit_kernel<<<dim3(1024/32, 512/32), dim3(32, 8)>>>(Wkv,  WKV_OFF,   1024);
    wsplit_kernel<<<dim3(512/32, 512/32), dim3(32, 8)>>>(Wproj, WPROJ_OFF, 512);
    // x*mask split
    xsplit_kernel<<<(MQ * CDIM) / 1024, 256>>>(x, mask);

    // q = x @ Wq + bq   (scores path: 1-mma bf16 is sufficient precision)
    gemm_tc<0,false><<<dim3(8, 128), 256, GSMEM>>>(bq, mask, nullptr, WQ_OFF, 0, 512, MQ);
    // k-half of kv (scores path: 1-mma)
    gemm_tc<1,false><<<dim3(8, 129), 256, GSMEM>>>(bkv, mask, nullptr, WKV_OFF, 0, 1024, MKV);
    // v-half of kv (value path: 3-mma for accuracy)
    gemm_tc<1,true><<<dim3(8, 129), 256, GSMEM>>>(bkv + 512, mask, nullptr, WKV_OFF + 512*512, 512, 1024, MKV);
    // windowed softmax attention (smem-tiled K/V, writes split bf16)
    attn_kernel<<<dim3(SEQ/32, NHEAD, BATCH), 256>>>();
    // out = (att @ Wproj + bproj) * mask  (3-mma)
    gemm_tc<2,true><<<dim3(8, 128), 256, GSMEM>>>(bproj, mask, out, WPROJ_OFF, 0, 512, MQ);
}